// round 6
// baseline (speedup 1.0000x reference)
#include <cuda_runtime.h>
#include <cstdint>

// FilterLayer: y[b,c,h,w] = sum_{i,j in 5x5} x_pad[b,c,h+i,w+j] * f[b,i*5+j,h,w]
// B=4, C=3, H=W=512, window=5, zero pad 2.
// R6: cp.async (LDGSTS.cg) pipeline for the dominant 105MB f stream.
// Latency hiding via the async-copy queue (~100KB in flight per SM) instead of
// register-resident loads (which capped MLP at regs=32 and pinned DRAM at ~56%).
// Stage = one filter row i (5 k-planes, 10KB). 3-buffer ring, depth 2.
// Compute keeps R4 shape: 2px/thread float2, conflict-free LDS.

#define IMG_H 512
#define IMG_W 512
#define TWX 32
#define TH  8
#define PX  2
#define TILE_W (TWX * PX)         // 64
#define HALO 2
#define TILE_R (TH + 2 * HALO)    // 12
#define TILE_C (TILE_W + 4)       // 68
#define NBUF 3
#define PRE  2
#define FS_PLANE (TH * TILE_W)    // 512 floats per k-plane tile
#define FS_STAGE (5 * FS_PLANE)   // 2560 floats per stage (one i, 5 j-taps)

__device__ __forceinline__ void cp_async16(uint32_t dst, const void* src) {
    asm volatile("cp.async.cg.shared.global [%0], [%1], 16;" :: "r"(dst), "l"(src));
}
__device__ __forceinline__ void cp_commit() {
    asm volatile("cp.async.commit_group;" ::: "memory");
}
template<int N> __device__ __forceinline__ void cp_wait() {
    asm volatile("cp.async.wait_group %0;" :: "n"(N) : "memory");
}

__global__ __launch_bounds__(256)
void filter_layer_kernel(const float* __restrict__ x,
                         const float* __restrict__ f,
                         float* __restrict__ out)
{
    __shared__ __align__(16) float fs[NBUF][FS_STAGE];   // 30 KB
    __shared__ __align__(8)  float xs[3][TILE_R][TILE_C]; // 9.8 KB

    const int b   = blockIdx.z;
    const int w0  = blockIdx.x * TILE_W;
    const int h0  = blockIdx.y * TH;
    const int tx  = threadIdx.x;          // 0..31
    const int ty  = threadIdx.y;          // 0..7
    const int tid = ty * TWX + tx;

    const int HW  = IMG_H * IMG_W;
    const float* fb = f + (size_t)b * 25 * HW;

    // ---- prologue: launch f stages 0..PRE-1 (each = 640 x 16B cp.async) ----
    #pragma unroll
    for (int s = 0; s < PRE; ++s) {
        #pragma unroll
        for (int u = 0; u < 3; ++u) {
            int t = tid + u * 256;
            if (u < 2 || t < FS_STAGE / 4) {             // 640 ops
                int kk = t >> 7;                          // k-plane within stage
                int r  = (t >> 4) & 7;                    // tile row
                int c4 = (t & 15) << 2;                   // float col (16B granule)
                const float* src = fb + (size_t)(5 * s + kk) * HW
                                      + (h0 + r) * IMG_W + w0 + c4;
                uint32_t dst = (uint32_t)__cvta_generic_to_shared(
                                   &fs[s][kk * FS_PLANE + r * TILE_W + c4]);
                cp_async16(dst, src);
            }
        }
        cp_commit();
    }

    // ---- stage x tile (small, direct LDG; overlaps with f transfers) ----
    const float* xb = x + (size_t)b * 3 * HW;
    for (int idx = tid; idx < 3 * TILE_R * TILE_C; idx += 256) {
        int c   = idx / (TILE_R * TILE_C);
        int rem = idx - c * (TILE_R * TILE_C);
        int r   = rem / TILE_C;
        int col = rem - r * TILE_C;
        int gr  = h0 + r - HALO;
        int gc  = w0 + col - HALO;
        float v = 0.0f;
        if ((unsigned)gr < (unsigned)IMG_H && (unsigned)gc < (unsigned)IMG_W)
            v = __ldg(xb + c * HW + gr * IMG_W + gc);
        xs[c][r][col] = v;
    }
    __syncthreads();   // xs visible (fs covered by cp_wait + bar in loop)

    const int p0 = 2 * tx;
    float2 a0 = make_float2(0.f, 0.f);
    float2 a1 = a0, a2 = a0;

    #pragma unroll
    for (int i = 0; i < 5; ++i) {
        cp_wait<PRE - 1>();      // stage i has landed (empty commits keep count)
        __syncthreads();

        const int buf = i % NBUF;

        // x rows for this i: 6 consecutive floats/channel, aligned -> LDS.64
        float xr0[6], xr1[6], xr2[6];
        {
            const float2* r0 = (const float2*)&xs[0][ty + i][p0];
            const float2* r1 = (const float2*)&xs[1][ty + i][p0];
            const float2* r2 = (const float2*)&xs[2][ty + i][p0];
            float2 u;
            u = r0[0]; xr0[0]=u.x; xr0[1]=u.y;
            u = r0[1]; xr0[2]=u.x; xr0[3]=u.y;
            u = r0[2]; xr0[4]=u.x; xr0[5]=u.y;
            u = r1[0]; xr1[0]=u.x; xr1[1]=u.y;
            u = r1[1]; xr1[2]=u.x; xr1[3]=u.y;
            u = r1[2]; xr1[4]=u.x; xr1[5]=u.y;
            u = r2[0]; xr2[0]=u.x; xr2[1]=u.y;
            u = r2[1]; xr2[2]=u.x; xr2[3]=u.y;
            u = r2[2]; xr2[4]=u.x; xr2[5]=u.y;
        }

        // f taps for this i from smem: stride FS_PLANE between j-planes
        const float* fsb = &fs[buf][ty * TILE_W + p0];
        #pragma unroll
        for (int j = 0; j < 5; ++j) {
            const float2 fv = *(const float2*)(fsb + j * FS_PLANE);
            a0.x = fmaf(xr0[j    ], fv.x, a0.x);
            a0.y = fmaf(xr0[j + 1], fv.y, a0.y);
            a1.x = fmaf(xr1[j    ], fv.x, a1.x);
            a1.y = fmaf(xr1[j + 1], fv.y, a1.y);
            a2.x = fmaf(xr2[j    ], fv.x, a2.x);
            a2.y = fmaf(xr2[j + 1], fv.y, a2.y);
        }

        // launch stage i+PRE (or empty group to keep wait_group counts valid)
        if (i + PRE < 5) {
            const int s  = i + PRE;
            const int nb = s % NBUF;
            #pragma unroll
            for (int u = 0; u < 3; ++u) {
                int t = tid + u * 256;
                if (u < 2 || t < FS_STAGE / 4) {
                    int kk = t >> 7;
                    int r  = (t >> 4) & 7;
                    int c4 = (t & 15) << 2;
                    const float* src = fb + (size_t)(5 * s + kk) * HW
                                          + (h0 + r) * IMG_W + w0 + c4;
                    uint32_t dst = (uint32_t)__cvta_generic_to_shared(
                                       &fs[nb][kk * FS_PLANE + r * TILE_W + c4]);
                    cp_async16(dst, src);
                }
            }
        }
        cp_commit();
    }

    // streaming stores (out written once; keep L2 for x)
    const int h   = h0 + ty;
    const int W2  = IMG_W / 2;
    const int HW2 = HW / 2;
    float2* o2 = (float2*)(out + (size_t)b * 3 * HW);
    const int obase = h * W2 + (w0 >> 1) + tx;
    __stcs(o2 + obase,           a0);
    __stcs(o2 + obase + HW2,     a1);
    __stcs(o2 + obase + 2 * HW2, a2);
}

extern "C" void kernel_launch(void* const* d_in, const int* in_sizes, int n_in,
                              void* d_out, int out_size)
{
    const float* x = (const float*)d_in[0];
    const float* f = (const float*)d_in[1];
    float* out = (float*)d_out;

    dim3 block(TWX, TH, 1);                        // 256 threads
    dim3 grid(IMG_W / TILE_W, IMG_H / TH, 4);      // 8 x 64 x 4 = 2048 blocks
    filter_layer_kernel<<<grid, block>>>(x, f, out);
}

// round 8
// speedup vs baseline: 1.2255x; 1.2255x over previous
#include <cuda_runtime.h>

// FilterLayer: y[b,c,h,w] = sum_{i,j in 5x5} x_pad[b,c,h+i,w+j] * f[b,i*5+j,h,w]
// B=4, C=3, H=W=512, window=5, zero pad 2.
// R7: R4 structure (2px/thread, float2, conflict-free LDS) + explicit
// double-row f prefetch. Registers are spent on f LDGs in flight (10 float2),
// not on unpack arrays: ~100KB/SM outstanding f bytes to fill the BW*latency
// product. launch_bounds(256,5) gives ptxas ~50 regs without R3-style collapse.

#define IMG_H 512
#define IMG_W 512
#define TWX 32
#define TH  8
#define TILE_W (TWX * 2)         // 64
#define HALO 2
#define TILE_R (TH + 2 * HALO)   // 12
#define TILE_C (TILE_W + 4)      // 68

__global__ __launch_bounds__(256, 5)
void filter_layer_kernel(const float* __restrict__ x,
                         const float* __restrict__ f,
                         float* __restrict__ out)
{
    __shared__ __align__(8) float xs[3][TILE_R][TILE_C];

    const int b  = blockIdx.z;
    const int w0 = blockIdx.x * TILE_W;
    const int h0 = blockIdx.y * TH;
    const int tx = threadIdx.x;
    const int ty = threadIdx.y;
    const int tid = ty * TWX + tx;

    const int HW  = IMG_H * IMG_W;
    const int W2  = IMG_W / 2;
    const int HW2 = HW / 2;

    const float2* f2 = (const float2*)(f + (size_t)b * 25 * HW);
    const int h     = h0 + ty;
    const int fbase = h * W2 + (w0 >> 1) + tx;

    // ---- issue row-0 f loads FIRST (before staging) so DRAM starts early ----
    float2 fb[5];
    #pragma unroll
    for (int j = 0; j < 5; ++j)
        fb[j] = __ldcs(f2 + (size_t)j * HW2 + fbase);

    // ---- Stage 3-channel x tile with halo (zero-padded at borders) ----
    const float* xb = x + (size_t)b * 3 * HW;
    for (int idx = tid; idx < 3 * TILE_R * TILE_C; idx += 256) {
        int c   = idx / (TILE_R * TILE_C);
        int rem = idx - c * (TILE_R * TILE_C);
        int r   = rem / TILE_C;
        int col = rem - r * TILE_C;
        int gr  = h0 + r - HALO;
        int gc  = w0 + col - HALO;
        float v = 0.0f;
        if ((unsigned)gr < (unsigned)IMG_H && (unsigned)gc < (unsigned)IMG_W)
            v = __ldg(xb + c * HW + gr * IMG_W + gc);
        xs[c][r][col] = v;
    }
    __syncthreads();

    const int p0 = 2 * tx;
    float2 a0 = make_float2(0.f, 0.f);
    float2 a1 = a0, a2 = a0;

    #pragma unroll
    for (int i = 0; i < 5; ++i) {
        // prefetch next row's 5 f2 values first (independent of this row's work)
        float2 fn[5];
        if (i < 4) {
            #pragma unroll
            for (int j = 0; j < 5; ++j)
                fn[j] = __ldcs(f2 + (size_t)((i + 1) * 5 + j) * HW2 + fbase);
        }

        // x row i: 6 consecutive floats per channel, 8B-aligned -> 3x LDS.64
        float xr0[6], xr1[6], xr2[6];
        {
            const float2* r0 = (const float2*)&xs[0][ty + i][p0];
            const float2* r1 = (const float2*)&xs[1][ty + i][p0];
            const float2* r2 = (const float2*)&xs[2][ty + i][p0];
            float2 u;
            u = r0[0]; xr0[0]=u.x; xr0[1]=u.y;
            u = r0[1]; xr0[2]=u.x; xr0[3]=u.y;
            u = r0[2]; xr0[4]=u.x; xr0[5]=u.y;
            u = r1[0]; xr1[0]=u.x; xr1[1]=u.y;
            u = r1[1]; xr1[2]=u.x; xr1[3]=u.y;
            u = r1[2]; xr1[4]=u.x; xr1[5]=u.y;
            u = r2[0]; xr2[0]=u.x; xr2[1]=u.y;
            u = r2[1]; xr2[2]=u.x; xr2[3]=u.y;
            u = r2[2]; xr2[4]=u.x; xr2[5]=u.y;
        }

        // consume row i from the prefetched registers
        #pragma unroll
        for (int j = 0; j < 5; ++j) {
            const float2 fv = fb[j];
            a0.x = fmaf(xr0[j    ], fv.x, a0.x);
            a0.y = fmaf(xr0[j + 1], fv.y, a0.y);
            a1.x = fmaf(xr1[j    ], fv.x, a1.x);
            a1.y = fmaf(xr1[j + 1], fv.y, a1.y);
            a2.x = fmaf(xr2[j    ], fv.x, a2.x);
            a2.y = fmaf(xr2[j + 1], fv.y, a2.y);
        }

        if (i < 4) {
            #pragma unroll
            for (int j = 0; j < 5; ++j) fb[j] = fn[j];
        }
    }

    // streaming stores (out written once; keep L2 for x)
    float2* o2 = (float2*)(out + (size_t)b * 3 * HW);
    const int obase = h * W2 + (w0 >> 1) + tx;
    __stcs(o2 + obase,           a0);
    __stcs(o2 + obase + HW2,     a1);
    __stcs(o2 + obase + 2 * HW2, a2);
}

extern "C" void kernel_launch(void* const* d_in, const int* in_sizes, int n_in,
                              void* d_out, int out_size)
{
    const float* x = (const float*)d_in[0];
    const float* f = (const float*)d_in[1];
    float* out = (float*)d_out;

    dim3 block(TWX, TH, 1);                        // 256 threads
    dim3 grid(IMG_W / TILE_W, IMG_H / TH, 4);      // 8 x 64 x 4 = 2048 blocks
    filter_layer_kernel<<<grid, block>>>(x, f, out);
}